// round 1
// baseline (speedup 1.0000x reference)
#include <cuda_runtime.h>
#include <cuda_bf16.h>

// Problem constants
#define B_SZ   2
#define S_LEN  2048
#define D_MOD  1024
#define HEADS  16
#define DHEAD  64
#define MROWS  (B_SZ * S_LEN)          // 4096
#define OUT_ELEMS  ((long)B_SZ * S_LEN * D_MOD)              // 4194304
#define ATTN_ELEMS ((long)B_SZ * HEADS * S_LEN * S_LEN)      // 134217728

// Scratch (static __device__ arrays: allocation-free per harness rules)
__device__ float g_q[MROWS * D_MOD];
__device__ float g_k[MROWS * D_MOD];
__device__ float g_v[MROWS * D_MOD];
__device__ float g_ctx[MROWS * D_MOD];
__device__ float g_attn_scratch[ATTN_ELEMS];

// ---------------------------------------------------------------------------
// GEMM-NT with bias: C[m][n] = sum_k A[m][k] * W[n][k] + bias[n]
// M=4096, N=1024, K=1024. BM=BN=64, BK=16, 256 threads, 4x4 per thread.
// ---------------------------------------------------------------------------
__global__ __launch_bounds__(256) void proj_kernel(
    const float* __restrict__ A, const float* __restrict__ W,
    const float* __restrict__ bias, float* __restrict__ C)
{
    const int M = MROWS, N = D_MOD, K = D_MOD;
    __shared__ float As[16][68];   // [k][m], padded
    __shared__ float Ws[16][68];   // [k][n]

    int tid = threadIdx.x;
    int tx = tid & 15, ty = tid >> 4;
    int m0 = blockIdx.y * 64, n0 = blockIdx.x * 64;

    float acc[4][4] = {};

    for (int k0 = 0; k0 < K; k0 += 16) {
        #pragma unroll
        for (int r = 0; r < 4; r++) {
            int idx = tid + r * 256;
            int row = idx >> 4;
            int col = idx & 15;
            As[col][row] = A[(long)(m0 + row) * K + k0 + col];
            Ws[col][row] = W[(long)(n0 + row) * K + k0 + col];
        }
        __syncthreads();
        #pragma unroll
        for (int kk = 0; kk < 16; kk++) {
            float4 a4 = *(const float4*)&As[kk][ty * 4];
            float4 b4 = *(const float4*)&Ws[kk][tx * 4];
            float av[4] = {a4.x, a4.y, a4.z, a4.w};
            float bv[4] = {b4.x, b4.y, b4.z, b4.w};
            #pragma unroll
            for (int i = 0; i < 4; i++)
                #pragma unroll
                for (int j = 0; j < 4; j++)
                    acc[i][j] += av[i] * bv[j];
        }
        __syncthreads();
    }

    #pragma unroll
    for (int i = 0; i < 4; i++) {
        int m = m0 + ty * 4 + i;
        #pragma unroll
        for (int j = 0; j < 4; j++) {
            int n = n0 + tx * 4 + j;
            C[(long)m * N + n] = acc[i][j] + bias[n];
        }
    }
}

// ---------------------------------------------------------------------------
// Scores: attn_logits[b,h,q,kk] = (q_head . k_head) / 8, masked.
// Per (b,h): 2048x2048 output, K-dim = 64. grid (32, 32, 32).
// ---------------------------------------------------------------------------
__global__ __launch_bounds__(256) void scores_kernel(
    const float* __restrict__ q, const float* __restrict__ k,
    const int* __restrict__ mask, float* __restrict__ attn)
{
    int bh = blockIdx.z;
    int b  = bh >> 4;
    int h  = bh & 15;
    const float* qh = q + (long)b * S_LEN * D_MOD + h * DHEAD;
    const float* kh = k + (long)b * S_LEN * D_MOD + h * DHEAD;
    float* outp = attn + (long)bh * S_LEN * S_LEN;

    int m0 = blockIdx.y * 64, n0 = blockIdx.x * 64;
    __shared__ float Qs[16][68];
    __shared__ float Ks[16][68];

    int tid = threadIdx.x;
    int tx = tid & 15, ty = tid >> 4;
    float acc[4][4] = {};

    for (int k0 = 0; k0 < DHEAD; k0 += 16) {
        #pragma unroll
        for (int r = 0; r < 4; r++) {
            int idx = tid + r * 256;
            int row = idx >> 4;
            int col = idx & 15;
            Qs[col][row] = qh[(long)(m0 + row) * D_MOD + k0 + col];
            Ks[col][row] = kh[(long)(n0 + row) * D_MOD + k0 + col];
        }
        __syncthreads();
        #pragma unroll
        for (int kk = 0; kk < 16; kk++) {
            float4 a4 = *(const float4*)&Qs[kk][ty * 4];
            float4 b4 = *(const float4*)&Ks[kk][tx * 4];
            float av[4] = {a4.x, a4.y, a4.z, a4.w};
            float bv[4] = {b4.x, b4.y, b4.z, b4.w};
            #pragma unroll
            for (int i = 0; i < 4; i++)
                #pragma unroll
                for (int j = 0; j < 4; j++)
                    acc[i][j] += av[i] * bv[j];
        }
        __syncthreads();
    }

    #pragma unroll
    for (int i = 0; i < 4; i++) {
        int m = m0 + ty * 4 + i;
        #pragma unroll
        for (int j = 0; j < 4; j++) {
            int n = n0 + tx * 4 + j;
            float v = acc[i][j] * 0.125f;              // 1/sqrt(64)
            if (mask[b * S_LEN + n] == 0) v = -1e9f;
            outp[(long)m * S_LEN + n] = v;
        }
    }
}

// ---------------------------------------------------------------------------
// Row softmax over 2048 elements, one block (256 threads) per row.
// ---------------------------------------------------------------------------
__global__ __launch_bounds__(256) void softmax_kernel(float* __restrict__ attn)
{
    long row = blockIdx.x;
    float* p = attn + row * S_LEN;
    int t = threadIdx.x;

    float v[8];
    float mx = -3.402823e38f;
    #pragma unroll
    for (int i = 0; i < 8; i++) {
        v[i] = p[t + i * 256];
        mx = fmaxf(mx, v[i]);
    }

    __shared__ float red[8];
    // warp reduce max
    #pragma unroll
    for (int o = 16; o > 0; o >>= 1)
        mx = fmaxf(mx, __shfl_xor_sync(0xffffffffu, mx, o));
    if ((t & 31) == 0) red[t >> 5] = mx;
    __syncthreads();
    if (t < 8) {
        float m2 = red[t];
        #pragma unroll
        for (int o = 4; o > 0; o >>= 1)
            m2 = fmaxf(m2, __shfl_xor_sync(0xffu, m2, o));
        if (t == 0) red[0] = m2;
    }
    __syncthreads();
    mx = red[0];

    float s = 0.f;
    #pragma unroll
    for (int i = 0; i < 8; i++) {
        v[i] = __expf(v[i] - mx);
        s += v[i];
    }
    __syncthreads();
    #pragma unroll
    for (int o = 16; o > 0; o >>= 1)
        s += __shfl_xor_sync(0xffffffffu, s, o);
    if ((t & 31) == 0) red[t >> 5] = s;
    __syncthreads();
    if (t < 8) {
        float s2 = red[t];
        #pragma unroll
        for (int o = 4; o > 0; o >>= 1)
            s2 += __shfl_xor_sync(0xffu, s2, o);
        if (t == 0) red[0] = s2;
    }
    __syncthreads();
    float inv = 1.f / red[0];

    #pragma unroll
    for (int i = 0; i < 8; i++)
        p[t + i * 256] = v[i] * inv;
}

// ---------------------------------------------------------------------------
// attn @ V : per (b,h) C[2048,64] = attn[2048,2048] @ v_head[2048,64]
// grid (32, 32): (m-tile, bh). BM=64, BN=64(=full Dh), BK=16.
// Writes merged ctx layout ctx[b*S+m][h*64+n].
// ---------------------------------------------------------------------------
__global__ __launch_bounds__(256) void av_kernel(
    const float* __restrict__ attn, const float* __restrict__ v,
    float* __restrict__ ctx)
{
    int bh = blockIdx.y;
    int b  = bh >> 4;
    int h  = bh & 15;
    const float* A  = attn + (long)bh * S_LEN * S_LEN;
    const float* vh = v + (long)b * S_LEN * D_MOD + h * DHEAD;
    float* outp = ctx + (long)b * S_LEN * D_MOD + h * DHEAD;

    int m0 = blockIdx.x * 64;
    __shared__ float As[16][68];   // [k][m]
    __shared__ float Bs[16][68];   // [k][n]

    int tid = threadIdx.x;
    int tx = tid & 15, ty = tid >> 4;
    float acc[4][4] = {};

    for (int k0 = 0; k0 < S_LEN; k0 += 16) {
        #pragma unroll
        for (int r = 0; r < 4; r++) {
            int idx = tid + r * 256;
            int arow = idx >> 4;       // 0..63 (m)
            int acol = idx & 15;       // 0..15 (k)
            As[acol][arow] = A[(long)(m0 + arow) * S_LEN + k0 + acol];
            int brow = idx >> 6;       // 0..15 (k)
            int bcol = idx & 63;       // 0..63 (n)
            Bs[brow][bcol] = vh[(long)(k0 + brow) * D_MOD + bcol];
        }
        __syncthreads();
        #pragma unroll
        for (int kk = 0; kk < 16; kk++) {
            float4 a4 = *(const float4*)&As[kk][ty * 4];
            float4 b4 = *(const float4*)&Bs[kk][tx * 4];
            float av[4] = {a4.x, a4.y, a4.z, a4.w};
            float bv[4] = {b4.x, b4.y, b4.z, b4.w};
            #pragma unroll
            for (int i = 0; i < 4; i++)
                #pragma unroll
                for (int j = 0; j < 4; j++)
                    acc[i][j] += av[i] * bv[j];
        }
        __syncthreads();
    }

    #pragma unroll
    for (int i = 0; i < 4; i++)
        #pragma unroll
        for (int j = 0; j < 4; j++)
            outp[(long)(m0 + ty * 4 + i) * D_MOD + tx * 4 + j] = acc[i][j];
}

// ---------------------------------------------------------------------------
extern "C" void kernel_launch(void* const* d_in, const int* in_sizes, int n_in,
                              void* d_out, int out_size)
{
    const float* Q    = (const float*)d_in[0];
    const float* K    = (const float*)d_in[1];
    const float* V    = (const float*)d_in[2];
    const int*   mask = (const int*)  d_in[3];
    const float* Wq   = (const float*)d_in[4];
    const float* bq   = (const float*)d_in[5];
    const float* Wk   = (const float*)d_in[6];
    const float* bk   = (const float*)d_in[7];
    const float* Wv   = (const float*)d_in[8];
    const float* bv   = (const float*)d_in[9];
    const float* Wo   = (const float*)d_in[10];
    const float* bo   = (const float*)d_in[11];

    float* out = (float*)d_out;

    // Resolve scratch device pointers
    float *q_p, *k_p, *v_p, *ctx_p, *attn_scr;
    cudaGetSymbolAddress((void**)&q_p,      g_q);
    cudaGetSymbolAddress((void**)&k_p,      g_k);
    cudaGetSymbolAddress((void**)&v_p,      g_v);
    cudaGetSymbolAddress((void**)&ctx_p,    g_ctx);
    cudaGetSymbolAddress((void**)&attn_scr, g_attn_scratch);

    // attn output placement: inside d_out if it holds (out, attn), else scratch
    float* attn = ((long)out_size >= OUT_ELEMS + ATTN_ELEMS)
                      ? (out + OUT_ELEMS) : attn_scr;

    dim3 projGrid(D_MOD / 64, MROWS / 64);   // (16, 64)
    proj_kernel<<<projGrid, 256>>>(Q, Wq, bq, q_p);
    proj_kernel<<<projGrid, 256>>>(K, Wk, bk, k_p);
    proj_kernel<<<projGrid, 256>>>(V, Wv, bv, v_p);

    dim3 scoreGrid(S_LEN / 64, S_LEN / 64, B_SZ * HEADS);  // (32,32,32)
    scores_kernel<<<scoreGrid, 256>>>(q_p, k_p, mask, attn);

    softmax_kernel<<<B_SZ * HEADS * S_LEN, 256>>>(attn);   // 65536 blocks

    dim3 avGrid(S_LEN / 64, B_SZ * HEADS);   // (32, 32)
    av_kernel<<<avGrid, 256>>>(attn, v_p, ctx_p);

    proj_kernel<<<projGrid, 256>>>(ctx_p, Wo, bo, out);
}

// round 2
// speedup vs baseline: 2.6514x; 2.6514x over previous
#include <cuda_runtime.h>

// Problem constants
#define B_SZ   2
#define S_LEN  2048
#define D_MOD  1024
#define HEADS  16
#define DHEAD  64
#define MROWS  (B_SZ * S_LEN)                                 // 4096
#define OUT_ELEMS  ((long)MROWS * D_MOD)                      // 4194304
#define ATTN_ELEMS ((long)B_SZ * HEADS * S_LEN * S_LEN)       // 134217728

// Scratch (static __device__ arrays: allocation-free per harness rules)
__device__ float g_q[MROWS * D_MOD];
__device__ float g_k[MROWS * D_MOD];
__device__ float g_v[MROWS * D_MOD];
__device__ float g_ctx[MROWS * D_MOD];
__device__ float g_attn_scratch[ATTN_ELEMS];

// ---------------------------------------------------------------------------
// tf32 helpers
// ---------------------------------------------------------------------------
__device__ __forceinline__ unsigned f2tf(float f) {
    unsigned u;
    asm("cvt.rna.tf32.f32 %0, %1;" : "=r"(u) : "f"(f));
    return u;
}

__device__ __forceinline__ void mma8(float* d, const unsigned* a, const unsigned* b) {
    asm volatile(
        "mma.sync.aligned.m16n8k8.row.col.f32.tf32.tf32.f32 "
        "{%0,%1,%2,%3}, {%4,%5,%6,%7}, {%8,%9}, {%0,%1,%2,%3};\n"
        : "+f"(d[0]), "+f"(d[1]), "+f"(d[2]), "+f"(d[3])
        : "r"(a[0]), "r"(a[1]), "r"(a[2]), "r"(a[3]), "r"(b[0]), "r"(b[1]));
}

__device__ __forceinline__ uint4 cvt4(float4 f) {
    return make_uint4(f2tf(f.x), f2tf(f.y), f2tf(f.z), f2tf(f.w));
}

// ---------------------------------------------------------------------------
// proj_mma: C[m][n] = A[m][k] * W[n][k] + bias[n]   (GEMM-NT)
// M=4096, N=1024, K=1024.  CTA 128x128, BK=32, 8 warps (2 m x 4 n),
// warp tile 64x32 -> 4x4 mma tiles of m16n8k8. tf32 inputs, fp32 accum.
// ---------------------------------------------------------------------------
__global__ __launch_bounds__(256, 2) void proj_mma(
    const float* __restrict__ A, const float* __restrict__ W,
    const float* __restrict__ bias, float* __restrict__ C)
{
    __shared__ unsigned As[128][36];   // [m][k], 36 % 32 == 4 -> conflict-free frag reads
    __shared__ unsigned Ws[128][36];   // [n][k]

    const int tid = threadIdx.x;
    const int wid = tid >> 5, lane = tid & 31;
    const int g = lane >> 2, c = lane & 3;
    const int wm = wid >> 2;          // 0..1
    const int wn = wid & 3;           // 0..3
    const int m0 = blockIdx.y * 128, n0 = blockIdx.x * 128;

    float acc[4][4][4] = {};

    for (int k0 = 0; k0 < D_MOD; k0 += 32) {
        #pragma unroll
        for (int i = 0; i < 4; i++) {                 // 1024 float4 per operand tile
            int idx = tid + i * 256;
            int row = idx >> 3, c4 = (idx & 7) * 4;
            float4 fa = *(const float4*)&A[(long)(m0 + row) * D_MOD + k0 + c4];
            float4 fw = *(const float4*)&W[(long)(n0 + row) * D_MOD + k0 + c4];
            *(uint4*)&As[row][c4] = cvt4(fa);
            *(uint4*)&Ws[row][c4] = cvt4(fw);
        }
        __syncthreads();

        #pragma unroll
        for (int ks = 0; ks < 4; ks++) {
            int kk = ks * 8;
            unsigned af[4][4], bf[4][2];
            #pragma unroll
            for (int mt = 0; mt < 4; mt++) {
                int r = wm * 64 + mt * 16 + g;
                af[mt][0] = As[r][kk + c];     af[mt][1] = As[r + 8][kk + c];
                af[mt][2] = As[r][kk + c + 4]; af[mt][3] = As[r + 8][kk + c + 4];
            }
            #pragma unroll
            for (int nt = 0; nt < 4; nt++) {
                int n = wn * 32 + nt * 8 + g;
                bf[nt][0] = Ws[n][kk + c];
                bf[nt][1] = Ws[n][kk + c + 4];
            }
            #pragma unroll
            for (int mt = 0; mt < 4; mt++)
                #pragma unroll
                for (int nt = 0; nt < 4; nt++)
                    mma8(acc[mt][nt], af[mt], bf[nt]);
        }
        __syncthreads();
    }

    #pragma unroll
    for (int nt = 0; nt < 4; nt++) {
        int col = n0 + wn * 32 + nt * 8 + 2 * c;
        float b0 = bias[col], b1 = bias[col + 1];
        #pragma unroll
        for (int mt = 0; mt < 4; mt++) {
            int r0 = m0 + wm * 64 + mt * 16 + g;
            float2 v0 = {acc[mt][nt][0] + b0, acc[mt][nt][1] + b1};
            float2 v1 = {acc[mt][nt][2] + b0, acc[mt][nt][3] + b1};
            *(float2*)&C[(long)r0 * D_MOD + col]       = v0;
            *(float2*)&C[(long)(r0 + 8) * D_MOD + col] = v1;
        }
    }
}

// ---------------------------------------------------------------------------
// scores_mma: per (b,h)  S[q][k] = (Qh . Kh) * 0.125, masked.
// Per-head GEMM-NT 2048x2048x64. CTA 128x128, K=64 (2 iters of BK=32).
// ---------------------------------------------------------------------------
__global__ __launch_bounds__(256, 2) void scores_mma(
    const float* __restrict__ q, const float* __restrict__ k,
    const int* __restrict__ mask, float* __restrict__ attn)
{
    __shared__ unsigned Qs[128][36];
    __shared__ unsigned Ks[128][36];

    const int bh = blockIdx.z;
    const int b = bh >> 4, h = bh & 15;
    const float* qh = q + (long)b * S_LEN * D_MOD + h * DHEAD;
    const float* kh = k + (long)b * S_LEN * D_MOD + h * DHEAD;
    float* outp = attn + (long)bh * S_LEN * S_LEN;

    const int tid = threadIdx.x;
    const int wid = tid >> 5, lane = tid & 31;
    const int g = lane >> 2, c = lane & 3;
    const int wm = wid >> 2, wn = wid & 3;
    const int m0 = blockIdx.y * 128, n0 = blockIdx.x * 128;

    float acc[4][4][4] = {};

    for (int k0 = 0; k0 < DHEAD; k0 += 32) {
        #pragma unroll
        for (int i = 0; i < 4; i++) {
            int idx = tid + i * 256;
            int row = idx >> 3, c4 = (idx & 7) * 4;
            float4 fq = *(const float4*)&qh[(long)(m0 + row) * D_MOD + k0 + c4];
            float4 fk = *(const float4*)&kh[(long)(n0 + row) * D_MOD + k0 + c4];
            *(uint4*)&Qs[row][c4] = cvt4(fq);
            *(uint4*)&Ks[row][c4] = cvt4(fk);
        }
        __syncthreads();

        #pragma unroll
        for (int ks = 0; ks < 4; ks++) {
            int kk = ks * 8;
            unsigned af[4][4], bf[4][2];
            #pragma unroll
            for (int mt = 0; mt < 4; mt++) {
                int r = wm * 64 + mt * 16 + g;
                af[mt][0] = Qs[r][kk + c];     af[mt][1] = Qs[r + 8][kk + c];
                af[mt][2] = Qs[r][kk + c + 4]; af[mt][3] = Qs[r + 8][kk + c + 4];
            }
            #pragma unroll
            for (int nt = 0; nt < 4; nt++) {
                int n = wn * 32 + nt * 8 + g;
                bf[nt][0] = Ks[n][kk + c];
                bf[nt][1] = Ks[n][kk + c + 4];
            }
            #pragma unroll
            for (int mt = 0; mt < 4; mt++)
                #pragma unroll
                for (int nt = 0; nt < 4; nt++)
                    mma8(acc[mt][nt], af[mt], bf[nt]);
        }
        __syncthreads();
    }

    #pragma unroll
    for (int nt = 0; nt < 4; nt++) {
        int col = n0 + wn * 32 + nt * 8 + 2 * c;
        bool z0 = (mask[b * S_LEN + col] == 0);
        bool z1 = (mask[b * S_LEN + col + 1] == 0);
        #pragma unroll
        for (int mt = 0; mt < 4; mt++) {
            int r0 = m0 + wm * 64 + mt * 16 + g;
            float2 v0 = {z0 ? -1e9f : acc[mt][nt][0] * 0.125f,
                         z1 ? -1e9f : acc[mt][nt][1] * 0.125f};
            float2 v1 = {z0 ? -1e9f : acc[mt][nt][2] * 0.125f,
                         z1 ? -1e9f : acc[mt][nt][3] * 0.125f};
            *(float2*)&outp[(long)r0 * S_LEN + col]       = v0;
            *(float2*)&outp[(long)(r0 + 8) * S_LEN + col] = v1;
        }
    }
}

// ---------------------------------------------------------------------------
// Row softmax over 2048 elements, one block (256 threads) per row.
// ---------------------------------------------------------------------------
__global__ __launch_bounds__(256) void softmax_kernel(float* __restrict__ attn)
{
    long row = blockIdx.x;
    float* p = attn + row * S_LEN;
    int t = threadIdx.x;

    float v[8];
    float mx = -3.402823e38f;
    #pragma unroll
    for (int i = 0; i < 8; i++) {
        v[i] = p[t + i * 256];
        mx = fmaxf(mx, v[i]);
    }

    __shared__ float red[8];
    #pragma unroll
    for (int o = 16; o > 0; o >>= 1)
        mx = fmaxf(mx, __shfl_xor_sync(0xffffffffu, mx, o));
    if ((t & 31) == 0) red[t >> 5] = mx;
    __syncthreads();
    if (t < 8) {
        float m2 = red[t];
        #pragma unroll
        for (int o = 4; o > 0; o >>= 1)
            m2 = fmaxf(m2, __shfl_xor_sync(0xffu, m2, o));
        if (t == 0) red[0] = m2;
    }
    __syncthreads();
    mx = red[0];

    float s = 0.f;
    #pragma unroll
    for (int i = 0; i < 8; i++) {
        v[i] = __expf(v[i] - mx);
        s += v[i];
    }
    __syncthreads();
    #pragma unroll
    for (int o = 16; o > 0; o >>= 1)
        s += __shfl_xor_sync(0xffffffffu, s, o);
    if ((t & 31) == 0) red[t >> 5] = s;
    __syncthreads();
    if (t < 8) {
        float s2 = red[t];
        #pragma unroll
        for (int o = 4; o > 0; o >>= 1)
            s2 += __shfl_xor_sync(0xffu, s2, o);
        if (t == 0) red[0] = s2;
    }
    __syncthreads();
    float inv = 1.f / red[0];

    #pragma unroll
    for (int i = 0; i < 8; i++)
        p[t + i * 256] = v[i] * inv;
}

// ---------------------------------------------------------------------------
// av_mma: per (b,h)  ctx[2048,64] = P[2048,2048] @ Vh[2048,64]   (GEMM-NN)
// CTA 128(m) x 64(n), BK=32. 8 warps (4 m x 2 n), warp tile 32x32 -> 2x4 tiles.
// ---------------------------------------------------------------------------
__global__ __launch_bounds__(256, 2) void av_mma(
    const float* __restrict__ attn, const float* __restrict__ v,
    float* __restrict__ ctx)
{
    __shared__ unsigned Ps[128][36];   // [m][k]
    __shared__ unsigned Vs[32][72];    // [k][n], 72 % 32 == 8 -> conflict-free B reads

    const int bh = blockIdx.y;
    const int b = bh >> 4, h = bh & 15;
    const float* P  = attn + (long)bh * S_LEN * S_LEN;
    const float* vh = v + (long)b * S_LEN * D_MOD + h * DHEAD;
    float* op = ctx + (long)b * S_LEN * D_MOD + h * DHEAD;

    const int tid = threadIdx.x;
    const int wid = tid >> 5, lane = tid & 31;
    const int g = lane >> 2, c = lane & 3;
    const int wm = wid >> 1;          // 0..3
    const int wn = wid & 1;           // 0..1
    const int m0 = blockIdx.x * 128;

    float acc[2][4][4] = {};

    for (int k0 = 0; k0 < S_LEN; k0 += 32) {
        #pragma unroll
        for (int i = 0; i < 4; i++) {                 // P tile: 1024 float4
            int idx = tid + i * 256;
            int row = idx >> 3, c4 = (idx & 7) * 4;
            float4 fp = *(const float4*)&P[(long)(m0 + row) * S_LEN + k0 + c4];
            *(uint4*)&Ps[row][c4] = cvt4(fp);
        }
        #pragma unroll
        for (int i = 0; i < 2; i++) {                 // V tile: 512 float4
            int idx = tid + i * 256;
            int row = idx >> 4, c4 = (idx & 15) * 4;
            float4 fv = *(const float4*)&vh[(long)(k0 + row) * D_MOD + c4];
            *(uint4*)&Vs[row][c4] = cvt4(fv);
        }
        __syncthreads();

        #pragma unroll
        for (int ks = 0; ks < 4; ks++) {
            int kk = ks * 8;
            unsigned af[2][4], bf[4][2];
            #pragma unroll
            for (int mt = 0; mt < 2; mt++) {
                int r = wm * 32 + mt * 16 + g;
                af[mt][0] = Ps[r][kk + c];     af[mt][1] = Ps[r + 8][kk + c];
                af[mt][2] = Ps[r][kk + c + 4]; af[mt][3] = Ps[r + 8][kk + c + 4];
            }
            #pragma unroll
            for (int nt = 0; nt < 4; nt++) {
                int n = wn * 32 + nt * 8 + g;
                bf[nt][0] = Vs[kk + c][n];
                bf[nt][1] = Vs[kk + c + 4][n];
            }
            #pragma unroll
            for (int mt = 0; mt < 2; mt++)
                #pragma unroll
                for (int nt = 0; nt < 4; nt++)
                    mma8(acc[mt][nt], af[mt], bf[nt]);
        }
        __syncthreads();
    }

    #pragma unroll
    for (int nt = 0; nt < 4; nt++) {
        int col = wn * 32 + nt * 8 + 2 * c;           // within head (0..63)
        #pragma unroll
        for (int mt = 0; mt < 2; mt++) {
            int r0 = m0 + wm * 32 + mt * 16 + g;
            float2 v0 = {acc[mt][nt][0], acc[mt][nt][1]};
            float2 v1 = {acc[mt][nt][2], acc[mt][nt][3]};
            *(float2*)&op[(long)r0 * D_MOD + col]       = v0;
            *(float2*)&op[(long)(r0 + 8) * D_MOD + col] = v1;
        }
    }
}

// ---------------------------------------------------------------------------
extern "C" void kernel_launch(void* const* d_in, const int* in_sizes, int n_in,
                              void* d_out, int out_size)
{
    const float* Q    = (const float*)d_in[0];
    const float* K    = (const float*)d_in[1];
    const float* V    = (const float*)d_in[2];
    const int*   mask = (const int*)  d_in[3];
    const float* Wq   = (const float*)d_in[4];
    const float* bq   = (const float*)d_in[5];
    const float* Wk   = (const float*)d_in[6];
    const float* bk   = (const float*)d_in[7];
    const float* Wv   = (const float*)d_in[8];
    const float* bv   = (const float*)d_in[9];
    const float* Wo   = (const float*)d_in[10];
    const float* bo   = (const float*)d_in[11];

    float* out = (float*)d_out;

    float *q_p, *k_p, *v_p, *ctx_p, *attn_scr;
    cudaGetSymbolAddress((void**)&q_p,      g_q);
    cudaGetSymbolAddress((void**)&k_p,      g_k);
    cudaGetSymbolAddress((void**)&v_p,      g_v);
    cudaGetSymbolAddress((void**)&ctx_p,    g_ctx);
    cudaGetSymbolAddress((void**)&attn_scr, g_attn_scratch);

    float* attn = ((long)out_size >= OUT_ELEMS + ATTN_ELEMS)
                      ? (out + OUT_ELEMS) : attn_scr;

    dim3 projGrid(D_MOD / 128, MROWS / 128);          // (8, 32)
    proj_mma<<<projGrid, 256>>>(Q, Wq, bq, q_p);
    proj_mma<<<projGrid, 256>>>(K, Wk, bk, k_p);
    proj_mma<<<projGrid, 256>>>(V, Wv, bv, v_p);

    dim3 scoreGrid(S_LEN / 128, S_LEN / 128, B_SZ * HEADS);   // (16,16,32)
    scores_mma<<<scoreGrid, 256>>>(q_p, k_p, mask, attn);

    softmax_kernel<<<B_SZ * HEADS * S_LEN, 256>>>(attn);

    dim3 avGrid(S_LEN / 128, B_SZ * HEADS);           // (16, 32)
    av_mma<<<avGrid, 256>>>(attn, v_p, ctx_p);

    proj_mma<<<projGrid, 256>>>(ctx_p, Wo, bo, out);
}